// round 1
// baseline (speedup 1.0000x reference)
#include <cuda_runtime.h>
#include <cuda_bf16.h>

// Problem constants
#define Bc  32
#define Nc  1024
#define Tc  64
#define Dc  32
#define NTc 1088   // N + T

// Scratch for the four projections (biases folded into the temporal-side ones)
__device__ float g_sa[Bc * Nc * Dc];  // spatial  @ st_w1[:32]
__device__ float g_tb[Bc * Nc * Dc];  // spatial  @ ts_w1[32:]
__device__ float g_sb[Bc * Tc * Dc];  // temporal @ st_w1[32:] + st_b1
__device__ float g_ta[Bc * Tc * Dc];  // temporal @ ts_w1[:32] + ts_b1

__device__ __forceinline__ float tanh_relu(float x) {
    // tanh(relu(x)); accurate fast path: tanh(x) = (1-e)/(1+e), e = exp(-2x)
    float e = __expf(-2.0f * x);
    float t = (1.0f - e) * __fdividef(1.0f, 1.0f + e);
    return x > 0.0f ? t : 0.0f;
}

__device__ __forceinline__ float sigmoid_fast(float x) {
    return __fdividef(1.0f, 1.0f + __expf(-x));
}

// ---------------------------------------------------------------------------
// Kernel 1: projections.  Rows 0..B*N-1 are spatial, then B*T temporal rows.
// Each block: 8 rows x 32 out-dims. Weight reads broadcast through L1.
// ---------------------------------------------------------------------------
__global__ void proj_kernel(const float* __restrict__ sp, const float* __restrict__ tp,
                            const float* __restrict__ st_w1, const float* __restrict__ st_b1,
                            const float* __restrict__ ts_w1, const float* __restrict__ ts_b1)
{
    __shared__ float xs[8][33];
    int d = threadIdx.x;          // 0..31
    int r = threadIdx.y;          // 0..7
    int gr = blockIdx.x * 8 + r;  // global row
    bool is_sp = gr < Bc * Nc;    // block-aligned split (32768 % 8 == 0)

    const float* src = is_sp ? (sp + (size_t)gr * Dc)
                             : (tp + (size_t)(gr - Bc * Nc) * Dc);
    xs[r][d] = src[d];
    __syncthreads();

    if (is_sp) {
        float a1 = 0.f, a2 = 0.f;
        #pragma unroll
        for (int k = 0; k < 32; ++k) {
            float x = xs[r][k];
            a1 = fmaf(x, st_w1[k * 32 + d], a1);           // st first half
            a2 = fmaf(x, ts_w1[(32 + k) * 32 + d], a2);    // ts second half
        }
        g_sa[gr * 32 + d] = a1;
        g_tb[gr * 32 + d] = a2;
    } else {
        int tr = gr - Bc * Nc;
        float a1 = st_b1[d], a2 = ts_b1[d];
        #pragma unroll
        for (int k = 0; k < 32; ++k) {
            float x = xs[r][k];
            a1 = fmaf(x, st_w1[(32 + k) * 32 + d], a1);    // st second half (+b1)
            a2 = fmaf(x, ts_w1[k * 32 + d], a2);           // ts first half (+b1)
        }
        g_sb[tr * 32 + d] = a1;
        g_ta[tr * 32 + d] = a2;
    }
}

// ---------------------------------------------------------------------------
// Kernel 2: top-left gram block  tanh(relu(S @ S^T)), 128x128 tile, 8x8/thread.
// ---------------------------------------------------------------------------
__global__ void __launch_bounds__(256, 2)
gram_tl_kernel(const float* __restrict__ X, float* __restrict__ out)
{
    __shared__ float As[128 * 33];
    __shared__ float Bs[128 * 33];
    int b  = blockIdx.z;
    int r0 = blockIdx.x * 128;
    int c0 = blockIdx.y * 128;
    int tx = threadIdx.x;                       // 0..15 -> col group
    int ty = threadIdx.y;                       // 0..15 -> row group
    int tid = ty * 16 + tx;

    const float* Xb = X + (size_t)b * Nc * Dc;
    for (int i = tid; i < 128 * 32; i += 256) {
        int row = i >> 5, k = i & 31;
        As[row * 33 + k] = Xb[(size_t)(r0 + row) * 32 + k];
        Bs[row * 33 + k] = Xb[(size_t)(c0 + row) * 32 + k];
    }
    __syncthreads();

    float c[8][8];
    #pragma unroll
    for (int i = 0; i < 8; ++i)
        #pragma unroll
        for (int j = 0; j < 8; ++j) c[i][j] = 0.f;

    #pragma unroll 4
    for (int k = 0; k < 32; ++k) {
        float av[8], bv[8];
        #pragma unroll
        for (int i = 0; i < 8; ++i) av[i] = As[(ty + 16 * i) * 33 + k]; // 2-addr bcast/warp
        #pragma unroll
        for (int j = 0; j < 8; ++j) bv[j] = Bs[(tx + 16 * j) * 33 + k]; // stride 33, CF
        #pragma unroll
        for (int i = 0; i < 8; ++i)
            #pragma unroll
            for (int j = 0; j < 8; ++j)
                c[i][j] = fmaf(av[i], bv[j], c[i][j]);
    }

    float* ob = out + (size_t)b * NTc * NTc;
    #pragma unroll
    for (int i = 0; i < 8; ++i) {
        size_t rowbase = (size_t)(r0 + ty + 16 * i) * NTc;
        #pragma unroll
        for (int j = 0; j < 8; ++j)
            ob[rowbase + (c0 + tx + 16 * j)] = tanh_relu(c[i][j]);
    }
}

// ---------------------------------------------------------------------------
// Kernel 3: bottom-right gram block tanh(relu(T @ T^T)), one block per batch.
// ---------------------------------------------------------------------------
__global__ void br_kernel(const float* __restrict__ tp, float* __restrict__ out)
{
    __shared__ float ts_s[64][33];
    int b = blockIdx.x, tid = threadIdx.x;
    const float* tb = tp + (size_t)b * Tc * Dc;
    for (int i = tid; i < 64 * 32; i += 256)
        ts_s[i >> 5][i & 31] = tb[i];
    __syncthreads();

    float* ob = out + (size_t)b * NTc * NTc;
    for (int it = 0; it < 16; ++it) {
        int idx = tid + 256 * it;
        int i = idx >> 6, j = idx & 63;
        float acc = 0.f;
        #pragma unroll
        for (int k = 0; k < 32; ++k)
            acc = fmaf(ts_s[i][k], ts_s[j][k], acc);
        ob[(size_t)(Nc + i) * NTc + (Nc + j)] = tanh_relu(acc);
    }
}

// ---------------------------------------------------------------------------
// Kernel 4/5: bilinear MLP blocks.
//   out[b,r,c] = tanh(relu(b2 + sum_d w2[d]*sigmoid(A[b,r,d] + B[b,c,d])))
// WHICH=0: st (rows=spatial N, cols=temporal T, placed at [0:N, N:])
// WHICH=1: ts (rows=temporal T, cols=spatial N, placed at [N:, 0:N])
// Tile: 16 rows x 64 cols per block, 4 outputs/thread.
// ---------------------------------------------------------------------------
template <int WHICH>
__global__ void __launch_bounds__(256)
pair_kernel(const float* __restrict__ w2, const float* __restrict__ b2,
            float* __restrict__ out)
{
    const int RA   = WHICH ? Tc : Nc;
    const int CB   = WHICH ? Nc : Tc;
    const int ROFF = WHICH ? Nc : 0;
    const int COFF = WHICH ? 0  : Nc;
    const float* Arow = WHICH ? g_ta : g_sa;
    const float* Bcol = WHICH ? g_tb : g_sb;

    __shared__ float rs[16][33];
    __shared__ float cs[64][33];
    __shared__ float w2s[32];

    int b  = blockIdx.z;
    int r0 = blockIdx.x * 16;
    int c0 = blockIdx.y * 64;
    int tid = threadIdx.x;

    for (int i = tid; i < 16 * 32; i += 256)
        rs[i >> 5][i & 31] = Arow[((size_t)b * RA + r0 + (i >> 5)) * 32 + (i & 31)];
    for (int i = tid; i < 64 * 32; i += 256)
        cs[i >> 5][i & 31] = Bcol[((size_t)b * CB + c0 + (i >> 5)) * 32 + (i & 31)];
    if (tid < 32) w2s[tid] = w2[tid];
    __syncthreads();

    int cc = tid & 63;   // column within tile (warp-contiguous -> CF smem, coalesced STG)
    int rg = tid >> 6;   // row group 0..3

    float acc[4] = {0.f, 0.f, 0.f, 0.f};
    #pragma unroll 8
    for (int d = 0; d < 32; ++d) {
        float bc = cs[cc][d];
        float w  = w2s[d];
        #pragma unroll
        for (int ii = 0; ii < 4; ++ii) {
            float x = rs[rg + 4 * ii][d] + bc;   // rs read is warp-broadcast
            acc[ii] = fmaf(w, sigmoid_fast(x), acc[ii]);
        }
    }

    float bb = b2[0];
    float* ob = out + (size_t)b * NTc * NTc;
    #pragma unroll
    for (int ii = 0; ii < 4; ++ii)
        ob[(size_t)(ROFF + r0 + rg + 4 * ii) * NTc + (COFF + c0 + cc)]
            = tanh_relu(acc[ii] + bb);
}

// ---------------------------------------------------------------------------
extern "C" void kernel_launch(void* const* d_in, const int* in_sizes, int n_in,
                              void* d_out, int out_size)
{
    const float* sp    = (const float*)d_in[0];
    const float* tp    = (const float*)d_in[1];
    const float* st_w1 = (const float*)d_in[2];
    const float* st_b1 = (const float*)d_in[3];
    const float* st_w2 = (const float*)d_in[4];
    const float* st_b2 = (const float*)d_in[5];
    const float* ts_w1 = (const float*)d_in[6];
    const float* ts_b1 = (const float*)d_in[7];
    const float* ts_w2 = (const float*)d_in[8];
    const float* ts_b2 = (const float*)d_in[9];
    float* out = (float*)d_out;

    proj_kernel<<<dim3((Bc * (Nc + Tc)) / 8), dim3(32, 8)>>>(sp, tp, st_w1, st_b1, ts_w1, ts_b1);
    gram_tl_kernel<<<dim3(Nc / 128, Nc / 128, Bc), dim3(16, 16)>>>(sp, out);
    br_kernel<<<Bc, 256>>>(tp, out);
    pair_kernel<0><<<dim3(Nc / 16, Tc / 64, Bc), 256>>>(st_w2, st_b2, out);
    pair_kernel<1><<<dim3(Tc / 16, Nc / 64, Bc), 256>>>(ts_w2, ts_b2, out);
}

// round 2
// speedup vs baseline: 1.1584x; 1.1584x over previous
#include <cuda_runtime.h>
#include <cuda_bf16.h>

// Problem constants
#define Bc  32
#define Nc  1024
#define Tc  64
#define Dc  32
#define NTc 1088   // N + T

// Scratch: the four projections, PRE-SCALED by 0.5 (for the tanh-sigmoid
// identity), temporal-side ones have 0.5*b1 folded in.
__device__ float g_sa[Bc * Nc * Dc];  // 0.5*(spatial  @ st_w1[:32])
__device__ float g_tb[Bc * Nc * Dc];  // 0.5*(spatial  @ ts_w1[32:])
__device__ float g_sb[Bc * Tc * Dc];  // 0.5*(temporal @ st_w1[32:] + st_b1)
__device__ float g_ta[Bc * Tc * Dc];  // 0.5*(temporal @ ts_w1[:32] + ts_b1)

__device__ __forceinline__ float tanh_ap(float x) {
    float y;
    asm("tanh.approx.f32 %0, %1;" : "=f"(y) : "f"(x));
    return y;
}
__device__ __forceinline__ float tanh_relu(float x) {
    return tanh_ap(fmaxf(x, 0.0f));
}

// ---------------------------------------------------------------------------
// Kernel 1: projections (scaled by 0.5).
// ---------------------------------------------------------------------------
__global__ void proj_kernel(const float* __restrict__ sp, const float* __restrict__ tp,
                            const float* __restrict__ st_w1, const float* __restrict__ st_b1,
                            const float* __restrict__ ts_w1, const float* __restrict__ ts_b1)
{
    __shared__ float xs[8][33];
    int d = threadIdx.x;          // 0..31
    int r = threadIdx.y;          // 0..7
    int gr = blockIdx.x * 8 + r;  // global row
    bool is_sp = gr < Bc * Nc;    // block-aligned split

    const float* src = is_sp ? (sp + (size_t)gr * Dc)
                             : (tp + (size_t)(gr - Bc * Nc) * Dc);
    xs[r][d] = src[d];
    __syncthreads();

    if (is_sp) {
        float a1 = 0.f, a2 = 0.f;
        #pragma unroll
        for (int k = 0; k < 32; ++k) {
            float x = xs[r][k];
            a1 = fmaf(x, st_w1[k * 32 + d], a1);
            a2 = fmaf(x, ts_w1[(32 + k) * 32 + d], a2);
        }
        g_sa[gr * 32 + d] = 0.5f * a1;
        g_tb[gr * 32 + d] = 0.5f * a2;
    } else {
        int tr = gr - Bc * Nc;
        float a1 = st_b1[d], a2 = ts_b1[d];
        #pragma unroll
        for (int k = 0; k < 32; ++k) {
            float x = xs[r][k];
            a1 = fmaf(x, st_w1[(32 + k) * 32 + d], a1);
            a2 = fmaf(x, ts_w1[k * 32 + d], a2);
        }
        g_sb[tr * 32 + d] = 0.5f * a1;
        g_ta[tr * 32 + d] = 0.5f * a2;
    }
}

// ---------------------------------------------------------------------------
// Fused kernel: gram-TL (packed FFMA2) + pair-st + pair-ts + gram-BR,
// block type interleaved via blockIdx.x % 3 so FMA and MUFU pipes overlap.
// ---------------------------------------------------------------------------
__global__ void __launch_bounds__(256, 2)
fused_kernel(const float* __restrict__ sp, const float* __restrict__ tp,
             const float* __restrict__ st_w2, const float* __restrict__ st_b2,
             const float* __restrict__ ts_w2, const float* __restrict__ ts_b2,
             float* __restrict__ out)
{
    __shared__ float sbuf[8448];   // 33 KB, carved per block type
    int idx = blockIdx.x;
    int tid = threadIdx.x;

    if (idx < 6144) {
        int type = idx % 3;
        int sub  = idx / 3;        // 0..2047 per type

        if (type == 0) {
            // ------------------- gram TL: tanh(relu(S @ S^T)) ---------------
            // 128x128 tile, 8 rows x (4 packed col-pairs) per thread.
            int b    = sub >> 6;
            int tile = sub & 63;
            int r0 = (tile & 7) << 7;
            int c0 = (tile >> 3) << 7;
            int tx = tid & 15;
            int ty = tid >> 4;

            float* As = sbuf;          // [128][33] row-major
            float* Bt = sbuf + 4224;   // [32][130] transposed: Bt[k][col]

            const float* Xb = sp + (size_t)b * Nc * Dc;
            for (int i = tid; i < 4096; i += 256) {
                int row = i >> 5, k = i & 31;
                As[row * 33 + k]  = Xb[(size_t)(r0 + row) * 32 + k];
                Bt[k * 130 + row] = Xb[(size_t)(c0 + row) * 32 + k];
            }
            __syncthreads();

            unsigned bt_u = (unsigned)__cvta_generic_to_shared(Bt) + tx * 8u;

            unsigned long long c2[8][4];
            #pragma unroll
            for (int i = 0; i < 8; ++i)
                #pragma unroll
                for (int p = 0; p < 4; ++p) c2[i][p] = 0ull;

            #pragma unroll 4
            for (int k = 0; k < 32; ++k) {
                float av[8];
                unsigned long long av2[8], bv2[4];
                #pragma unroll
                for (int i = 0; i < 8; ++i) av[i] = As[(ty + 16 * i) * 33 + k];
                #pragma unroll
                for (int i = 0; i < 8; ++i)
                    asm("mov.b64 %0, {%1, %1};" : "=l"(av2[i]) : "f"(av[i]));
                #pragma unroll
                for (int p = 0; p < 4; ++p)
                    asm("ld.shared.b64 %0, [%1];" : "=l"(bv2[p])
                        : "r"(bt_u + (unsigned)(k * 520 + p * 128)));
                #pragma unroll
                for (int i = 0; i < 8; ++i)
                    #pragma unroll
                    for (int p = 0; p < 4; ++p)
                        asm("fma.rn.f32x2 %0, %1, %2, %0;"
                            : "+l"(c2[i][p]) : "l"(av2[i]), "l"(bv2[p]));
            }

            float* ob = out + (size_t)b * NTc * NTc;
            #pragma unroll
            for (int i = 0; i < 8; ++i) {
                size_t base = (size_t)(r0 + ty + 16 * i) * NTc + c0 + tx * 2;
                #pragma unroll
                for (int p = 0; p < 4; ++p) {
                    float lo, hi;
                    asm("mov.b64 {%0, %1}, %2;" : "=f"(lo), "=f"(hi) : "l"(c2[i][p]));
                    float2 v;
                    v.x = tanh_relu(lo);
                    v.y = tanh_relu(hi);
                    *reinterpret_cast<float2*>(ob + base + 32 * p) = v;
                }
            }
        } else {
            // ------------------- bilinear MLP pair blocks -------------------
            // out = tanh(relu( wconst + 0.5*sum_d w2[d]*tanh(A+B) ))
            // where A,B are the 0.5-scaled projections.
            int RA, CB, ROFF, COFF, r0, c0, b;
            const float *Arow, *Bcol, *w2, *b2;
            if (type == 1) {           // st: rows spatial, cols temporal
                r0 = (sub & 63) * 16;  c0 = 0;  b = sub >> 6;
                RA = Nc; CB = Tc; ROFF = 0; COFF = Nc;
                Arow = g_sa; Bcol = g_sb; w2 = st_w2; b2 = st_b2;
            } else {                   // ts: rows temporal, cols spatial
                int rt = sub & 3, ct = (sub >> 2) & 15;
                r0 = rt * 16; c0 = ct * 64; b = sub >> 6;
                RA = Tc; CB = Nc; ROFF = Nc; COFF = 0;
                Arow = g_ta; Bcol = g_tb; w2 = ts_w2; b2 = ts_b2;
            }

            float* rs  = sbuf;          // [16][33]
            float* cs  = sbuf + 528;    // [64][33]
            float* w2s = sbuf + 2640;   // [32]
            float* wcp = sbuf + 2672;   // [1] wconst

            for (int i = tid; i < 512; i += 256)
                rs[(i >> 5) * 33 + (i & 31)] =
                    Arow[((size_t)b * RA + r0 + (i >> 5)) * 32 + (i & 31)];
            for (int i = tid; i < 2048; i += 256)
                cs[(i >> 5) * 33 + (i & 31)] =
                    Bcol[((size_t)b * CB + c0 + (i >> 5)) * 32 + (i & 31)];
            if (tid < 32) w2s[tid] = w2[tid];
            __syncthreads();
            if (tid == 0) {
                float s = 0.f;
                #pragma unroll
                for (int d = 0; d < 32; ++d) s += w2s[d];
                wcp[0] = fmaf(0.5f, s, b2[0]);   // b2 + 0.5*sum(w2)
            }
            __syncthreads();

            int cc = tid & 63;   // column in tile
            int rg = tid >> 6;   // row group 0..3

            float acc[4] = {0.f, 0.f, 0.f, 0.f};
            #pragma unroll 8
            for (int d = 0; d < 32; ++d) {
                float bcv = cs[cc * 33 + d];
                float w   = w2s[d];
                #pragma unroll
                for (int ii = 0; ii < 4; ++ii) {
                    float t = tanh_ap(rs[(rg + 4 * ii) * 33 + d] + bcv);
                    acc[ii] = fmaf(w, t, acc[ii]);
                }
            }

            float wconst = wcp[0];
            float* ob = out + (size_t)b * NTc * NTc;
            #pragma unroll
            for (int ii = 0; ii < 4; ++ii)
                ob[(size_t)(ROFF + r0 + rg + 4 * ii) * NTc + (COFF + c0 + cc)]
                    = tanh_relu(fmaf(0.5f, acc[ii], wconst));
        }
    } else {
        // ------------------- gram BR: tanh(relu(T @ T^T)) -------------------
        int b = idx - 6144;
        float* ts_s = sbuf;   // [64][33]
        const float* tb = tp + (size_t)b * Tc * Dc;
        for (int i = tid; i < 2048; i += 256)
            ts_s[(i >> 5) * 33 + (i & 31)] = tb[i];
        __syncthreads();

        float* ob = out + (size_t)b * NTc * NTc;
        for (int it = 0; it < 16; ++it) {
            int e = tid + 256 * it;
            int i = e >> 6, j = e & 63;
            float acc = 0.f;
            #pragma unroll
            for (int k = 0; k < 32; ++k)
                acc = fmaf(ts_s[i * 33 + k], ts_s[j * 33 + k], acc);
            ob[(size_t)(Nc + i) * NTc + (Nc + j)] = tanh_relu(acc);
        }
    }
}

// ---------------------------------------------------------------------------
extern "C" void kernel_launch(void* const* d_in, const int* in_sizes, int n_in,
                              void* d_out, int out_size)
{
    const float* sp    = (const float*)d_in[0];
    const float* tp    = (const float*)d_in[1];
    const float* st_w1 = (const float*)d_in[2];
    const float* st_b1 = (const float*)d_in[3];
    const float* st_w2 = (const float*)d_in[4];
    const float* st_b2 = (const float*)d_in[5];
    const float* ts_w1 = (const float*)d_in[6];
    const float* ts_b1 = (const float*)d_in[7];
    const float* ts_w2 = (const float*)d_in[8];
    const float* ts_b2 = (const float*)d_in[9];
    float* out = (float*)d_out;

    proj_kernel<<<dim3((Bc * (Nc + Tc)) / 8), dim3(32, 8)>>>(sp, tp, st_w1, st_b1, ts_w1, ts_b1);
    fused_kernel<<<6176, 256>>>(sp, tp, st_w2, st_b2, ts_w2, ts_b2, out);
}

// round 3
// speedup vs baseline: 1.3531x; 1.1680x over previous
#include <cuda_runtime.h>
#include <cuda_bf16.h>

// Problem constants
#define Bc  32
#define Nc  1024
#define Tc  64
#define Dc  32
#define NTc 1088   // N + T

// Scratch: the four projections, PRE-SCALED by 0.5 (tanh-sigmoid identity);
// temporal-side ones have 0.5*b1 folded in.
__device__ float g_sa[Bc * Nc * Dc];  // 0.5*(spatial  @ st_w1[:32])
__device__ float g_tb[Bc * Nc * Dc];  // 0.5*(spatial  @ ts_w1[32:])
__device__ float g_sb[Bc * Tc * Dc];  // 0.5*(temporal @ st_w1[32:] + st_b1)
__device__ float g_ta[Bc * Tc * Dc];  // 0.5*(temporal @ ts_w1[:32] + ts_b1)

__device__ __forceinline__ float tanh_ap(float x) {
    float y;
    asm("tanh.approx.f32 %0, %1;" : "=f"(y) : "f"(x));
    return y;
}
__device__ __forceinline__ float tanh_relu(float x) {
    return tanh_ap(fmaxf(x, 0.0f));
}

// ---------------------------------------------------------------------------
// Kernel 1: projections (scaled by 0.5).
// ---------------------------------------------------------------------------
__global__ void proj_kernel(const float* __restrict__ sp, const float* __restrict__ tp,
                            const float* __restrict__ st_w1, const float* __restrict__ st_b1,
                            const float* __restrict__ ts_w1, const float* __restrict__ ts_b1)
{
    __shared__ float xs[8][33];
    int d = threadIdx.x;          // 0..31
    int r = threadIdx.y;          // 0..7
    int gr = blockIdx.x * 8 + r;  // global row
    bool is_sp = gr < Bc * Nc;    // block-aligned split

    const float* src = is_sp ? (sp + (size_t)gr * Dc)
                             : (tp + (size_t)(gr - Bc * Nc) * Dc);
    xs[r][d] = src[d];
    __syncthreads();

    if (is_sp) {
        float a1 = 0.f, a2 = 0.f;
        #pragma unroll
        for (int k = 0; k < 32; ++k) {
            float x = xs[r][k];
            a1 = fmaf(x, st_w1[k * 32 + d], a1);
            a2 = fmaf(x, ts_w1[(32 + k) * 32 + d], a2);
        }
        g_sa[gr * 32 + d] = 0.5f * a1;
        g_tb[gr * 32 + d] = 0.5f * a2;
    } else {
        int tr = gr - Bc * Nc;
        float a1 = st_b1[d], a2 = ts_b1[d];
        #pragma unroll
        for (int k = 0; k < 32; ++k) {
            float x = xs[r][k];
            a1 = fmaf(x, st_w1[(32 + k) * 32 + d], a1);
            a2 = fmaf(x, ts_w1[k * 32 + d], a2);
        }
        g_sb[tr * 32 + d] = 0.5f * a1;
        g_ta[tr * 32 + d] = 0.5f * a2;
    }
}

// ---------------------------------------------------------------------------
// Fused kernel: gram-TL (packed FFMA2, 64x128 tile) + pair-st + pair-ts +
// gram-BR. Block type from idx&1 so every SM runs an FMA/MUFU mix.
// Register budget: <=64 (4 CTAs/SM).
// ---------------------------------------------------------------------------
__global__ void __launch_bounds__(256, 4)
fused_kernel(const float* __restrict__ sp, const float* __restrict__ tp,
             const float* __restrict__ st_w2, const float* __restrict__ st_b2,
             const float* __restrict__ ts_w2, const float* __restrict__ ts_b2,
             float* __restrict__ out)
{
    __shared__ float sbuf[6272];   // 25 KB, carved per block type
    int idx = blockIdx.x;
    int tid = threadIdx.x;

    if (idx < 8192) {
        int type = idx & 1;
        int sub  = idx >> 1;       // 0..4095 per type

        if (type == 0) {
            // ------------- gram TL: tanh(relu(S @ S^T)), 64x128 tile --------
            // thread: 4 rows x 4 packed col-pairs (32 outputs, 16 packed acc).
            int b    = sub >> 7;            // 32 batches
            int tile = sub & 127;           // 16 row-tiles x 8 col-tiles
            int r0 = (tile & 15) << 6;
            int c0 = (tile >> 4) << 7;
            int tx = tid & 15;
            int ty = tid >> 4;

            float* As = sbuf;           // [64][33]
            float* Bt = sbuf + 2112;    // [32][130] transposed: Bt[k][col]

            const float* Xb = sp + (size_t)b * Nc * Dc;
            for (int i = tid; i < 2048; i += 256) {
                int row = i >> 5, k = i & 31;
                As[row * 33 + k] = Xb[(size_t)(r0 + row) * 32 + k];
            }
            for (int i = tid; i < 4096; i += 256) {
                int row = i >> 5, k = i & 31;
                Bt[k * 130 + row] = Xb[(size_t)(c0 + row) * 32 + k];
            }
            __syncthreads();

            unsigned bt_u = (unsigned)__cvta_generic_to_shared(Bt) + tx * 8u;

            unsigned long long c2[4][4];
            #pragma unroll
            for (int i = 0; i < 4; ++i)
                #pragma unroll
                for (int p = 0; p < 4; ++p) c2[i][p] = 0ull;

            #pragma unroll 8
            for (int k = 0; k < 32; ++k) {
                unsigned long long av2[4], bv2[4];
                #pragma unroll
                for (int i = 0; i < 4; ++i) {
                    float a = As[(ty + 16 * i) * 33 + k];
                    asm("mov.b64 %0, {%1, %1};" : "=l"(av2[i]) : "f"(a));
                }
                #pragma unroll
                for (int p = 0; p < 4; ++p)
                    asm("ld.shared.b64 %0, [%1];" : "=l"(bv2[p])
                        : "r"(bt_u + (unsigned)(k * 520 + p * 128)));
                #pragma unroll
                for (int i = 0; i < 4; ++i)
                    #pragma unroll
                    for (int p = 0; p < 4; ++p)
                        asm("fma.rn.f32x2 %0, %1, %2, %0;"
                            : "+l"(c2[i][p]) : "l"(av2[i]), "l"(bv2[p]));
            }

            float* ob = out + (size_t)b * NTc * NTc;
            #pragma unroll
            for (int i = 0; i < 4; ++i) {
                size_t base = (size_t)(r0 + ty + 16 * i) * NTc + c0 + tx * 2;
                #pragma unroll
                for (int p = 0; p < 4; ++p) {
                    float lo, hi;
                    asm("mov.b64 {%0, %1}, %2;" : "=f"(lo), "=f"(hi) : "l"(c2[i][p]));
                    float2 v;
                    v.x = tanh_relu(lo);
                    v.y = tanh_relu(hi);
                    *reinterpret_cast<float2*>(ob + base + 32 * p) = v;
                }
            }
        } else {
            // ------------------- bilinear MLP pair blocks -------------------
            // out = tanh(relu( wconst + 0.5*sum_d w2[d]*tanh(A+B) ))
            int RA, CB, ROFF, COFF, r0, c0, b;
            const float *Arow, *Bcol, *w2, *b2;
            if (sub < 2048) {          // st: rows spatial, cols temporal
                r0 = (sub & 63) * 16;  c0 = 0;  b = sub >> 6;
                RA = Nc; CB = Tc; ROFF = 0; COFF = Nc;
                Arow = g_sa; Bcol = g_sb; w2 = st_w2; b2 = st_b2;
            } else {                   // ts: rows temporal, cols spatial
                int s2 = sub - 2048;
                int rt = s2 & 3, ct = (s2 >> 2) & 15;
                r0 = rt * 16; c0 = ct * 64; b = s2 >> 6;
                RA = Tc; CB = Nc; ROFF = Nc; COFF = 0;
                Arow = g_ta; Bcol = g_tb; w2 = ts_w2; b2 = ts_b2;
            }

            float* rs  = sbuf;          // [16][33]
            float* cs  = sbuf + 528;    // [64][33]
            float* w2s = sbuf + 2640;   // [32]
            float* wcp = sbuf + 2672;   // [1]

            for (int i = tid; i < 512; i += 256)
                rs[(i >> 5) * 33 + (i & 31)] =
                    Arow[((size_t)b * RA + r0 + (i >> 5)) * 32 + (i & 31)];
            for (int i = tid; i < 2048; i += 256)
                cs[(i >> 5) * 33 + (i & 31)] =
                    Bcol[((size_t)b * CB + c0 + (i >> 5)) * 32 + (i & 31)];
            if (tid < 32) w2s[tid] = w2[tid];
            __syncthreads();
            if (tid == 0) {
                float s = 0.f;
                #pragma unroll
                for (int d = 0; d < 32; ++d) s += w2s[d];
                wcp[0] = fmaf(0.5f, s, b2[0]);   // b2 + 0.5*sum(w2)
            }
            __syncthreads();

            int cc = tid & 63;   // column in tile
            int rg = tid >> 6;   // row group 0..3

            float acc[4] = {0.f, 0.f, 0.f, 0.f};
            #pragma unroll 8
            for (int d = 0; d < 32; ++d) {
                float bcv = cs[cc * 33 + d];
                float w   = w2s[d];
                #pragma unroll
                for (int ii = 0; ii < 4; ++ii) {
                    float t = tanh_ap(rs[(rg + 4 * ii) * 33 + d] + bcv);
                    acc[ii] = fmaf(w, t, acc[ii]);
                }
            }

            float wconst = wcp[0];
            float* ob = out + (size_t)b * NTc * NTc;
            #pragma unroll
            for (int ii = 0; ii < 4; ++ii)
                ob[(size_t)(ROFF + r0 + rg + 4 * ii) * NTc + (COFF + c0 + cc)]
                    = tanh_relu(fmaf(0.5f, acc[ii], wconst));
        }
    } else {
        // ------------------- gram BR: tanh(relu(T @ T^T)) -------------------
        int b = idx - 8192;
        float* ts_s = sbuf;   // [64][33]
        const float* tb = tp + (size_t)b * Tc * Dc;
        for (int i = tid; i < 2048; i += 256)
            ts_s[(i >> 5) * 33 + (i & 31)] = tb[i];
        __syncthreads();

        float* ob = out + (size_t)b * NTc * NTc;
        for (int it = 0; it < 16; ++it) {
            int e = tid + 256 * it;
            int i = e >> 6, j = e & 63;
            float acc = 0.f;
            #pragma unroll
            for (int k = 0; k < 32; ++k)
                acc = fmaf(ts_s[i * 33 + k], ts_s[j * 33 + k], acc);
            ob[(size_t)(Nc + i) * NTc + (Nc + j)] = tanh_relu(acc);
        }
    }
}

// ---------------------------------------------------------------------------
extern "C" void kernel_launch(void* const* d_in, const int* in_sizes, int n_in,
                              void* d_out, int out_size)
{
    const float* sp    = (const float*)d_in[0];
    const float* tp    = (const float*)d_in[1];
    const float* st_w1 = (const float*)d_in[2];
    const float* st_b1 = (const float*)d_in[3];
    const float* st_w2 = (const float*)d_in[4];
    const float* st_b2 = (const float*)d_in[5];
    const float* ts_w1 = (const float*)d_in[6];
    const float* ts_b1 = (const float*)d_in[7];
    const float* ts_w2 = (const float*)d_in[8];
    const float* ts_b2 = (const float*)d_in[9];
    float* out = (float*)d_out;

    proj_kernel<<<dim3((Bc * (Nc + Tc)) / 8), dim3(32, 8)>>>(sp, tp, st_w1, st_b1, ts_w1, ts_b1);
    fused_kernel<<<8224, 256>>>(sp, tp, st_w2, st_b2, ts_w2, ts_b2, out);
}

// round 4
// speedup vs baseline: 1.4478x; 1.0700x over previous
#include <cuda_runtime.h>
#include <cuda_bf16.h>

// Problem constants
#define Bc  32
#define Nc  1024
#define Tc  64
#define Dc  32
#define NTc 1088   // N + T

// Scratch: the four projections, PRE-SCALED by 0.5 (tanh-sigmoid identity);
// temporal-side ones have 0.5*b1 folded in.
__device__ float g_sa[Bc * Nc * Dc];  // 0.5*(spatial  @ st_w1[:32])
__device__ float g_tb[Bc * Nc * Dc];  // 0.5*(spatial  @ ts_w1[32:])
__device__ float g_sb[Bc * Tc * Dc];  // 0.5*(temporal @ st_w1[32:] + st_b1)
__device__ float g_ta[Bc * Tc * Dc];  // 0.5*(temporal @ ts_w1[:32] + ts_b1)

__device__ __forceinline__ float tanh_ap(float x) {
    float y;
    asm("tanh.approx.f32 %0, %1;" : "=f"(y) : "f"(x));
    return y;
}
__device__ __forceinline__ float tanh_relu(float x) {
    return tanh_ap(fmaxf(x, 0.0f));
}

// ---------------------------------------------------------------------------
// Kernel 1: projections (scaled by 0.5). 32 rows per block, weights staged
// in smem once, 4 rows x 2 projections per thread.
// ---------------------------------------------------------------------------
__global__ void __launch_bounds__(256)
proj_kernel(const float* __restrict__ sp, const float* __restrict__ tp,
            const float* __restrict__ st_w1, const float* __restrict__ st_b1,
            const float* __restrict__ ts_w1, const float* __restrict__ ts_b1)
{
    __shared__ float xs[32 * 33];
    __shared__ float wa[32 * 32];
    __shared__ float wb[32 * 32];

    int tid = threadIdx.y * 32 + threadIdx.x;
    int gr0 = blockIdx.x * 32;
    bool is_sp = gr0 < Bc * Nc;       // 32-row aligned split

    const float* src = is_sp ? (sp + (size_t)gr0 * Dc)
                             : (tp + (size_t)(gr0 - Bc * Nc) * Dc);
    for (int i = tid; i < 1024; i += 256)
        xs[(i >> 5) * 33 + (i & 31)] = src[i];
    for (int i = tid; i < 1024; i += 256) {
        int k = i >> 5, dd = i & 31;
        if (is_sp) {
            wa[i] = st_w1[k * 32 + dd];          // st first half
            wb[i] = ts_w1[(32 + k) * 32 + dd];   // ts second half
        } else {
            wa[i] = st_w1[(32 + k) * 32 + dd];   // st second half
            wb[i] = ts_w1[k * 32 + dd];          // ts first half
        }
    }
    __syncthreads();

    int d  = threadIdx.x;
    int ty = threadIdx.y;

    float acc1[4], acc2[4];
    float b1a = is_sp ? 0.f : st_b1[d];
    float b1b = is_sp ? 0.f : ts_b1[d];
    #pragma unroll
    for (int rr = 0; rr < 4; ++rr) { acc1[rr] = b1a; acc2[rr] = b1b; }

    #pragma unroll 4
    for (int k = 0; k < 32; ++k) {
        float wav = wa[k * 32 + d];
        float wbv = wb[k * 32 + d];
        #pragma unroll
        for (int rr = 0; rr < 4; ++rr) {
            float x = xs[(ty + 8 * rr) * 33 + k];
            acc1[rr] = fmaf(x, wav, acc1[rr]);
            acc2[rr] = fmaf(x, wbv, acc2[rr]);
        }
    }

    float* o1 = is_sp ? g_sa : g_sb;
    float* o2 = is_sp ? g_tb : g_ta;
    size_t base = is_sp ? (size_t)gr0 : (size_t)(gr0 - Bc * Nc);
    #pragma unroll
    for (int rr = 0; rr < 4; ++rr) {
        size_t r = base + ty + 8 * rr;
        o1[r * 32 + d] = 0.5f * acc1[rr];
        o2[r * 32 + d] = 0.5f * acc2[rr];
    }
}

// ---------------------------------------------------------------------------
// Fused kernel: gram-TL (packed FFMA2, 64x128 tile, vectorized k-major smem)
// + pair-st + pair-ts + gram-BR. Block type from idx&1 for pipe mixing.
// ---------------------------------------------------------------------------
__global__ void __launch_bounds__(256, 4)
fused_kernel(const float* __restrict__ sp, const float* __restrict__ tp,
             const float* __restrict__ st_w2, const float* __restrict__ st_b2,
             const float* __restrict__ ts_w2, const float* __restrict__ ts_b2,
             float* __restrict__ out)
{
    __shared__ __align__(16) float sbuf[6400];   // 25.6 KB
    int idx = blockIdx.x;
    int tid = threadIdx.x;

    if (idx < 8192) {
        int type = idx & 1;
        int sub  = idx >> 1;       // 0..4095 per type

        if (type == 0) {
            // ------------- gram TL: tanh(relu(S @ S^T)), 64x128 tile --------
            // thread: rows 4ty..4ty+3, cols {4tx..4tx+3, 64+4tx..64+4tx+3}.
            int b    = sub >> 7;            // 32 batches
            int tile = sub & 127;           // 16 row-tiles x 8 col-tiles
            int r0 = (tile & 15) << 6;
            int c0 = (tile >> 4) << 7;
            int tx = tid & 15;
            int ty = tid >> 4;

            float* At = sbuf;           // [32][68]  k-major
            float* Bt = sbuf + 2176;    // [32][132] k-major

            const float* Xb = sp + (size_t)b * Nc * Dc;
            for (int i = tid; i < 2048; i += 256) {
                int row = i >> 5, k = i & 31;
                At[k * 68 + row] = Xb[(size_t)(r0 + row) * 32 + k];
            }
            for (int i = tid; i < 4096; i += 256) {
                int row = i >> 5, k = i & 31;
                Bt[k * 132 + row] = Xb[(size_t)(c0 + row) * 32 + k];
            }
            __syncthreads();

            unsigned at_u = (unsigned)__cvta_generic_to_shared(At) + ty * 16u;
            unsigned bt_u = (unsigned)__cvta_generic_to_shared(Bt) + tx * 16u;

            unsigned long long c2[4][4];
            #pragma unroll
            for (int i = 0; i < 4; ++i)
                #pragma unroll
                for (int p = 0; p < 4; ++p) c2[i][p] = 0ull;

            #pragma unroll 4
            for (int k = 0; k < 32; ++k) {
                float a0, a1, a2, a3;
                asm("ld.shared.v4.b32 {%0,%1,%2,%3}, [%4];"
                    : "=f"(a0), "=f"(a1), "=f"(a2), "=f"(a3)
                    : "r"(at_u + (unsigned)(k * 272)));
                unsigned long long av2[4], bv2[4];
                asm("mov.b64 %0, {%1, %1};" : "=l"(av2[0]) : "f"(a0));
                asm("mov.b64 %0, {%1, %1};" : "=l"(av2[1]) : "f"(a1));
                asm("mov.b64 %0, {%1, %1};" : "=l"(av2[2]) : "f"(a2));
                asm("mov.b64 %0, {%1, %1};" : "=l"(av2[3]) : "f"(a3));
                asm("ld.shared.v2.b64 {%0,%1}, [%2];"
                    : "=l"(bv2[0]), "=l"(bv2[1])
                    : "r"(bt_u + (unsigned)(k * 528)));
                asm("ld.shared.v2.b64 {%0,%1}, [%2];"
                    : "=l"(bv2[2]), "=l"(bv2[3])
                    : "r"(bt_u + (unsigned)(k * 528 + 256)));
                #pragma unroll
                for (int i = 0; i < 4; ++i)
                    #pragma unroll
                    for (int p = 0; p < 4; ++p)
                        asm("fma.rn.f32x2 %0, %1, %2, %0;"
                            : "+l"(c2[i][p]) : "l"(av2[i]), "l"(bv2[p]));
            }

            float* ob = out + (size_t)b * NTc * NTc;
            #pragma unroll
            for (int i = 0; i < 4; ++i) {
                float* orow = ob + (size_t)(r0 + 4 * ty + i) * NTc + c0;
                #pragma unroll
                for (int h = 0; h < 2; ++h) {    // h=0: cols 4tx, h=1: 64+4tx
                    float l0, h0, l1, h1;
                    asm("mov.b64 {%0, %1}, %2;" : "=f"(l0), "=f"(h0) : "l"(c2[i][2*h]));
                    asm("mov.b64 {%0, %1}, %2;" : "=f"(l1), "=f"(h1) : "l"(c2[i][2*h+1]));
                    float4 v;
                    v.x = tanh_relu(l0); v.y = tanh_relu(h0);
                    v.z = tanh_relu(l1); v.w = tanh_relu(h1);
                    *reinterpret_cast<float4*>(orow + 64 * h + 4 * tx) = v;
                }
            }
        } else {
            // ------------------- bilinear MLP pair blocks -------------------
            // out = tanh(relu( wconst + 0.5*sum_d w2[d]*tanh(A+B) ))
            int RA, CB, ROFF, COFF, r0, c0, b;
            const float *Arow, *Bcol, *w2, *b2;
            if (sub < 2048) {          // st: rows spatial, cols temporal
                r0 = (sub & 63) * 16;  c0 = 0;  b = sub >> 6;
                RA = Nc; CB = Tc; ROFF = 0; COFF = Nc;
                Arow = g_sa; Bcol = g_sb; w2 = st_w2; b2 = st_b2;
            } else {                   // ts: rows temporal, cols spatial
                int s2 = sub - 2048;
                int rt = s2 & 3, ct = (s2 >> 2) & 15;
                r0 = rt * 16; c0 = ct * 64; b = s2 >> 6;
                RA = Tc; CB = Nc; ROFF = Nc; COFF = 0;
                Arow = g_ta; Bcol = g_tb; w2 = ts_w2; b2 = ts_b2;
            }

            float* rs  = sbuf;          // [16][33]
            float* cs  = sbuf + 528;    // [64][33]
            float* w2s = sbuf + 2640;   // [32]
            float* wcp = sbuf + 2672;   // [1]

            for (int i = tid; i < 512; i += 256)
                rs[(i >> 5) * 33 + (i & 31)] =
                    Arow[((size_t)b * RA + r0 + (i >> 5)) * 32 + (i & 31)];
            for (int i = tid; i < 2048; i += 256)
                cs[(i >> 5) * 33 + (i & 31)] =
                    Bcol[((size_t)b * CB + c0 + (i >> 5)) * 32 + (i & 31)];
            if (tid < 32) w2s[tid] = w2[tid];
            __syncthreads();
            if (tid == 0) {
                float s = 0.f;
                #pragma unroll
                for (int d = 0; d < 32; ++d) s += w2s[d];
                wcp[0] = fmaf(0.5f, s, b2[0]);   // b2 + 0.5*sum(w2)
            }
            __syncthreads();

            int cc = tid & 63;   // column in tile
            int rg = tid >> 6;   // row group 0..3

            float acc[4] = {0.f, 0.f, 0.f, 0.f};
            #pragma unroll 8
            for (int d = 0; d < 32; ++d) {
                float bcv = cs[cc * 33 + d];
                float w   = w2s[d];
                #pragma unroll
                for (int ii = 0; ii < 4; ++ii) {
                    float t = tanh_ap(rs[(rg + 4 * ii) * 33 + d] + bcv);
                    acc[ii] = fmaf(w, t, acc[ii]);
                }
            }

            float wconst = wcp[0];
            float* ob = out + (size_t)b * NTc * NTc;
            #pragma unroll
            for (int ii = 0; ii < 4; ++ii)
                ob[(size_t)(ROFF + r0 + rg + 4 * ii) * NTc + (COFF + c0 + cc)]
                    = tanh_relu(fmaf(0.5f, acc[ii], wconst));
        }
    } else {
        // ------------------- gram BR: tanh(relu(T @ T^T)) -------------------
        int b = idx - 8192;
        float* ts_s = sbuf;   // [64][33]
        const float* tb = tp + (size_t)b * Tc * Dc;
        for (int i = tid; i < 2048; i += 256)
            ts_s[(i >> 5) * 33 + (i & 31)] = tb[i];
        __syncthreads();

        float* ob = out + (size_t)b * NTc * NTc;
        for (int it = 0; it < 16; ++it) {
            int e = tid + 256 * it;
            int i = e >> 6, j = e & 63;
            float acc = 0.f;
            #pragma unroll
            for (int k = 0; k < 32; ++k)
                acc = fmaf(ts_s[i * 33 + k], ts_s[j * 33 + k], acc);
            ob[(size_t)(Nc + i) * NTc + (Nc + j)] = tanh_relu(acc);
        }
    }
}

// ---------------------------------------------------------------------------
extern "C" void kernel_launch(void* const* d_in, const int* in_sizes, int n_in,
                              void* d_out, int out_size)
{
    const float* sp    = (const float*)d_in[0];
    const float* tp    = (const float*)d_in[1];
    const float* st_w1 = (const float*)d_in[2];
    const float* st_b1 = (const float*)d_in[3];
    const float* st_w2 = (const float*)d_in[4];
    const float* st_b2 = (const float*)d_in[5];
    const float* ts_w1 = (const float*)d_in[6];
    const float* ts_b1 = (const float*)d_in[7];
    const float* ts_w2 = (const float*)d_in[8];
    const float* ts_b2 = (const float*)d_in[9];
    float* out = (float*)d_out;

    proj_kernel<<<dim3((Bc * (Nc + Tc)) / 32), dim3(32, 8)>>>(sp, tp, st_w1, st_b1, ts_w1, ts_b1);
    fused_kernel<<<8224, 256>>>(sp, tp, st_w2, st_b2, ts_w2, ts_b2, out);
}

// round 5
// speedup vs baseline: 1.6090x; 1.1113x over previous
#include <cuda_runtime.h>
#include <cuda_bf16.h>

// Problem constants
#define Bc  32
#define Nc  1024
#define Tc  64
#define Dc  32
#define NTc 1088   // N + T

// Scratch: the four projections, PRE-SCALED by 0.5 (tanh-sigmoid identity);
// temporal-side ones have 0.5*b1 folded in.
__device__ float g_sa[Bc * Nc * Dc];
__device__ float g_tb[Bc * Nc * Dc];
__device__ float g_sb[Bc * Tc * Dc];
__device__ float g_ta[Bc * Tc * Dc];

__device__ __forceinline__ float tanh_ap(float x) {
    float y;
    asm("tanh.approx.f32 %0, %1;" : "=f"(y) : "f"(x));
    return y;
}
__device__ __forceinline__ float tanh_relu(float x) {
    return tanh_ap(fmaxf(x, 0.0f));
}

// ---------------------------------------------------------------------------
// Kernel 1: projections (scaled by 0.5). 32 rows/block, weights staged once.
// ---------------------------------------------------------------------------
__global__ void __launch_bounds__(256)
proj_kernel(const float* __restrict__ sp, const float* __restrict__ tp,
            const float* __restrict__ st_w1, const float* __restrict__ st_b1,
            const float* __restrict__ ts_w1, const float* __restrict__ ts_b1)
{
    __shared__ float xs[32 * 33];
    __shared__ float wa[32 * 32];
    __shared__ float wb[32 * 32];

    int tid = threadIdx.y * 32 + threadIdx.x;
    int gr0 = blockIdx.x * 32;
    bool is_sp = gr0 < Bc * Nc;

    const float* src = is_sp ? (sp + (size_t)gr0 * Dc)
                             : (tp + (size_t)(gr0 - Bc * Nc) * Dc);
    for (int i = tid; i < 1024; i += 256)
        xs[(i >> 5) * 33 + (i & 31)] = src[i];
    for (int i = tid; i < 1024; i += 256) {
        int k = i >> 5, dd = i & 31;
        if (is_sp) {
            wa[i] = st_w1[k * 32 + dd];
            wb[i] = ts_w1[(32 + k) * 32 + dd];
        } else {
            wa[i] = st_w1[(32 + k) * 32 + dd];
            wb[i] = ts_w1[k * 32 + dd];
        }
    }
    __syncthreads();

    int d  = threadIdx.x;
    int ty = threadIdx.y;

    float acc1[4], acc2[4];
    float b1a = is_sp ? 0.f : st_b1[d];
    float b1b = is_sp ? 0.f : ts_b1[d];
    #pragma unroll
    for (int rr = 0; rr < 4; ++rr) { acc1[rr] = b1a; acc2[rr] = b1b; }

    #pragma unroll 4
    for (int k = 0; k < 32; ++k) {
        float wav = wa[k * 32 + d];
        float wbv = wb[k * 32 + d];
        #pragma unroll
        for (int rr = 0; rr < 4; ++rr) {
            float x = xs[(ty + 8 * rr) * 33 + k];
            acc1[rr] = fmaf(x, wav, acc1[rr]);
            acc2[rr] = fmaf(x, wbv, acc2[rr]);
        }
    }

    float* o1 = is_sp ? g_sa : g_sb;
    float* o2 = is_sp ? g_tb : g_ta;
    size_t base = is_sp ? (size_t)gr0 : (size_t)(gr0 - Bc * Nc);
    #pragma unroll
    for (int rr = 0; rr < 4; ++rr) {
        size_t r = base + ty + 8 * rr;
        o1[r * 32 + d] = 0.5f * acc1[rr];
        o2[r * 32 + d] = 0.5f * acc2[rr];
    }
}

// ---------------------------------------------------------------------------
// Fused kernel. Work list (6432 blocks):
//   idx < 6400: period-25 interleave — r<9: gram half-block (2304 total,
//               upper-triangle supertiles, mirrored), else pair (4096 total).
//   idx >= 6400: gram BR (32).
// ---------------------------------------------------------------------------
__global__ void __launch_bounds__(256, 4)
fused_kernel(const float* __restrict__ sp, const float* __restrict__ tp,
             const float* __restrict__ st_w2, const float* __restrict__ st_b2,
             const float* __restrict__ ts_w2, const float* __restrict__ ts_b2,
             float* __restrict__ out)
{
    __shared__ __align__(16) float sbuf[6400];   // 25.6 KB
    int idx = blockIdx.x;
    int tid = threadIdx.x;

    if (idx < 6400) {
        int q = idx / 25, r = idx % 25;

        if (r < 9) {
            // ------------- gram TL: tanh(relu(S @ S^T)), 64x128 tile --------
            int g = q * 9 + r;          // 0..2303
            int b = g / 72, t = g % 72;

            int r0, c0; bool mirror;
            if (t < 16) {               // diagonal supertile halves
                int st = t >> 1;
                r0 = st * 128 + (t & 1) * 64;
                c0 = st * 128;
                mirror = false;
            } else {                    // off-diagonal upper supertiles
                int o = t - 16;
                int u = o >> 1;         // 0..27 -> (R,C), R<C
                int R = 0, rem = u;
                while (rem >= 7 - R) { rem -= 7 - R; ++R; }
                int C = R + 1 + rem;
                r0 = R * 128 + (o & 1) * 64;
                c0 = C * 128;
                mirror = true;
            }

            int tx = tid & 15;
            int ty = tid >> 4;

            float* At = sbuf;           // [32][68]  k-major
            float* Bt = sbuf + 2176;    // [32][132] k-major

            const float* Xb = sp + (size_t)b * Nc * Dc;
            for (int i = tid; i < 2048; i += 256) {
                int row = i >> 5, k = i & 31;
                At[k * 68 + row] = Xb[(size_t)(r0 + row) * 32 + k];
            }
            for (int i = tid; i < 4096; i += 256) {
                int row = i >> 5, k = i & 31;
                Bt[k * 132 + row] = Xb[(size_t)(c0 + row) * 32 + k];
            }
            __syncthreads();

            unsigned at_u = (unsigned)__cvta_generic_to_shared(At) + ty * 16u;
            unsigned bt_u = (unsigned)__cvta_generic_to_shared(Bt) + tx * 16u;

            unsigned long long c2[4][4];
            #pragma unroll
            for (int i = 0; i < 4; ++i)
                #pragma unroll
                for (int p = 0; p < 4; ++p) c2[i][p] = 0ull;

            #pragma unroll 4
            for (int k = 0; k < 32; ++k) {
                float a0, a1, a2, a3;
                asm("ld.shared.v4.b32 {%0,%1,%2,%3}, [%4];"
                    : "=f"(a0), "=f"(a1), "=f"(a2), "=f"(a3)
                    : "r"(at_u + (unsigned)(k * 272)));
                unsigned long long av2[4], bv2[4];
                asm("mov.b64 %0, {%1, %1};" : "=l"(av2[0]) : "f"(a0));
                asm("mov.b64 %0, {%1, %1};" : "=l"(av2[1]) : "f"(a1));
                asm("mov.b64 %0, {%1, %1};" : "=l"(av2[2]) : "f"(a2));
                asm("mov.b64 %0, {%1, %1};" : "=l"(av2[3]) : "f"(a3));
                asm("ld.shared.v2.b64 {%0,%1}, [%2];"
                    : "=l"(bv2[0]), "=l"(bv2[1])
                    : "r"(bt_u + (unsigned)(k * 528)));
                asm("ld.shared.v2.b64 {%0,%1}, [%2];"
                    : "=l"(bv2[2]), "=l"(bv2[3])
                    : "r"(bt_u + (unsigned)(k * 528 + 256)));
                #pragma unroll
                for (int i = 0; i < 4; ++i)
                    #pragma unroll
                    for (int p = 0; p < 4; ++p)
                        asm("fma.rn.f32x2 %0, %1, %2, %0;"
                            : "+l"(c2[i][p]) : "l"(av2[i]), "l"(bv2[p]));
            }
            __syncthreads();   // sbuf reuse for transpose staging below

            float* ob = out + (size_t)b * NTc * NTc;

            #pragma unroll
            for (int h = 0; h < 2; ++h) {       // column halves 0-63, 64-127
                // unpack + activation
                float va[4][4];                 // [row i][col c]
                #pragma unroll
                for (int i = 0; i < 4; ++i) {
                    float l0, h0, l1, h1;
                    asm("mov.b64 {%0, %1}, %2;" : "=f"(l0), "=f"(h0) : "l"(c2[i][2*h]));
                    asm("mov.b64 {%0, %1}, %2;" : "=f"(l1), "=f"(h1) : "l"(c2[i][2*h+1]));
                    va[i][0] = tanh_relu(l0); va[i][1] = tanh_relu(h0);
                    va[i][2] = tanh_relu(l1); va[i][3] = tanh_relu(h1);
                }
                // normal store
                #pragma unroll
                for (int i = 0; i < 4; ++i) {
                    float4 v;
                    v.x = va[i][0]; v.y = va[i][1]; v.z = va[i][2]; v.w = va[i][3];
                    *reinterpret_cast<float4*>(
                        ob + (size_t)(r0 + 4 * ty + i) * NTc + c0 + 64 * h + 4 * tx) = v;
                }
                if (mirror) {
                    // stage transposed: sbuf[col][row], col = 4tx+c in chunk
                    #pragma unroll
                    for (int c = 0; c < 4; ++c) {
                        float4 v;
                        v.x = va[0][c]; v.y = va[1][c]; v.z = va[2][c]; v.w = va[3][c];
                        *reinterpret_cast<float4*>(sbuf + (4 * tx + c) * 68 + 4 * ty) = v;
                    }
                    __syncthreads();
                    // coalesced mirror write: warp w -> mirror rows 8w..8w+7
                    int w = tid >> 5, l = tid & 31;
                    int sr = l >> 4, off = (l & 15) * 4;
                    #pragma unroll
                    for (int j = 0; j < 4; ++j) {
                        int row = 8 * w + 2 * j + sr;    // col-in-chunk
                        float4 v = *reinterpret_cast<float4*>(sbuf + row * 68 + off);
                        *reinterpret_cast<float4*>(
                            ob + (size_t)(c0 + 64 * h + row) * NTc + r0 + off) = v;
                    }
                    __syncthreads();
                }
            }
        } else {
            // ------------------- bilinear MLP pair blocks -------------------
            int p = q * 16 + (r - 9);   // 0..4095
            int RA, CB, ROFF, COFF, r0, c0, b;
            const float *Arow, *Bcol, *w2, *b2;
            if (p < 2048) {            // st: rows spatial, cols temporal
                r0 = (p & 63) * 16;  c0 = 0;  b = p >> 6;
                RA = Nc; CB = Tc; ROFF = 0; COFF = Nc;
                Arow = g_sa; Bcol = g_sb; w2 = st_w2; b2 = st_b2;
            } else {                   // ts: rows temporal, cols spatial
                int s2 = p - 2048;
                r0 = (s2 & 3) * 16; c0 = ((s2 >> 2) & 15) * 64; b = s2 >> 6;
                RA = Tc; CB = Nc; ROFF = Nc; COFF = 0;
                Arow = g_ta; Bcol = g_tb; w2 = ts_w2; b2 = ts_b2;
            }

            float* rs  = sbuf;          // [16][33]
            float* cs  = sbuf + 528;    // [64][33]
            float* w2s = sbuf + 2640;   // [32]
            float* wcp = sbuf + 2672;   // [1]

            for (int i = tid; i < 512; i += 256)
                rs[(i >> 5) * 33 + (i & 31)] =
                    Arow[((size_t)b * RA + r0 + (i >> 5)) * 32 + (i & 31)];
            for (int i = tid; i < 2048; i += 256)
                cs[(i >> 5) * 33 + (i & 31)] =
                    Bcol[((size_t)b * CB + c0 + (i >> 5)) * 32 + (i & 31)];
            if (tid < 32) w2s[tid] = w2[tid];
            __syncthreads();
            if (tid == 0) {
                float s = 0.f;
                #pragma unroll
                for (int d = 0; d < 32; ++d) s += w2s[d];
                wcp[0] = fmaf(0.5f, s, b2[0]);   // b2 + 0.5*sum(w2)
            }
            __syncthreads();

            int cc = tid & 63;
            int rg = tid >> 6;

            float acc[4] = {0.f, 0.f, 0.f, 0.f};
            #pragma unroll 8
            for (int d = 0; d < 32; ++d) {
                float bcv = cs[cc * 33 + d];
                float w   = w2s[d];
                #pragma unroll
                for (int ii = 0; ii < 4; ++ii) {
                    float t = tanh_ap(rs[(rg + 4 * ii) * 33 + d] + bcv);
                    acc[ii] = fmaf(w, t, acc[ii]);
                }
            }

            float wconst = wcp[0];
            float* ob = out + (size_t)b * NTc * NTc;
            #pragma unroll
            for (int ii = 0; ii < 4; ++ii)
                ob[(size_t)(ROFF + r0 + rg + 4 * ii) * NTc + (COFF + c0 + cc)]
                    = tanh_relu(fmaf(0.5f, acc[ii], wconst));
        }
    } else {
        // ------------------- gram BR: tanh(relu(T @ T^T)) -------------------
        int b = idx - 6400;
        float* ts_s = sbuf;   // [64][33]
        const float* tb = tp + (size_t)b * Tc * Dc;
        for (int i = tid; i < 2048; i += 256)
            ts_s[(i >> 5) * 33 + (i & 31)] = tb[i];
        __syncthreads();

        float* ob = out + (size_t)b * NTc * NTc;
        for (int it = 0; it < 16; ++it) {
            int e = tid + 256 * it;
            int i = e >> 6, j = e & 63;
            float acc = 0.f;
            #pragma unroll
            for (int k = 0; k < 32; ++k)
                acc = fmaf(ts_s[i * 33 + k], ts_s[j * 33 + k], acc);
            ob[(size_t)(Nc + i) * NTc + (Nc + j)] = tanh_relu(acc);
        }
    }
}

// ---------------------------------------------------------------------------
extern "C" void kernel_launch(void* const* d_in, const int* in_sizes, int n_in,
                              void* d_out, int out_size)
{
    const float* sp    = (const float*)d_in[0];
    const float* tp    = (const float*)d_in[1];
    const float* st_w1 = (const float*)d_in[2];
    const float* st_b1 = (const float*)d_in[3];
    const float* st_w2 = (const float*)d_in[4];
    const float* st_b2 = (const float*)d_in[5];
    const float* ts_w1 = (const float*)d_in[6];
    const float* ts_b1 = (const float*)d_in[7];
    const float* ts_w2 = (const float*)d_in[8];
    const float* ts_b2 = (const float*)d_in[9];
    float* out = (float*)d_out;

    proj_kernel<<<dim3((Bc * (Nc + Tc)) / 32), dim3(32, 8)>>>(sp, tp, st_w1, st_b1, ts_w1, ts_b1);
    fused_kernel<<<6432, 256>>>(sp, tp, st_w2, st_b2, ts_w2, ts_b2, out);
}

// round 6
// speedup vs baseline: 1.8412x; 1.1443x over previous
#include <cuda_runtime.h>
#include <cuda_bf16.h>

// Problem constants
#define Bc  32
#define Nc  1024
#define Tc  64
#define Dc  32
#define NTc 1088   // N + T

// Scratch: the four projections, PRE-SCALED by 0.5 (tanh-sigmoid identity);
// temporal-side ones have 0.5*b1 folded in.
__device__ float g_sa[Bc * Nc * Dc];
__device__ float g_tb[Bc * Nc * Dc];
__device__ float g_sb[Bc * Tc * Dc];
__device__ float g_ta[Bc * Tc * Dc];

__device__ __forceinline__ float tanh_ap(float x) {
    float y;
    asm("tanh.approx.f32 %0, %1;" : "=f"(y) : "f"(x));
    return y;
}
__device__ __forceinline__ float tanh_relu(float x) {
    return tanh_ap(fmaxf(x, 0.0f));
}

// ---------------------------------------------------------------------------
// Kernel 1: projections (scaled by 0.5). 32 rows/block, weights staged once.
// ---------------------------------------------------------------------------
__global__ void __launch_bounds__(256)
proj_kernel(const float* __restrict__ sp, const float* __restrict__ tp,
            const float* __restrict__ st_w1, const float* __restrict__ st_b1,
            const float* __restrict__ ts_w1, const float* __restrict__ ts_b1)
{
    __shared__ float xs[32 * 33];
    __shared__ float wa[32 * 32];
    __shared__ float wb[32 * 32];

    int tid = threadIdx.y * 32 + threadIdx.x;
    int gr0 = blockIdx.x * 32;
    bool is_sp = gr0 < Bc * Nc;

    const float* src = is_sp ? (sp + (size_t)gr0 * Dc)
                             : (tp + (size_t)(gr0 - Bc * Nc) * Dc);
    for (int i = tid; i < 1024; i += 256)
        xs[(i >> 5) * 33 + (i & 31)] = src[i];
    for (int i = tid; i < 1024; i += 256) {
        int k = i >> 5, dd = i & 31;
        if (is_sp) {
            wa[i] = st_w1[k * 32 + dd];
            wb[i] = ts_w1[(32 + k) * 32 + dd];
        } else {
            wa[i] = st_w1[(32 + k) * 32 + dd];
            wb[i] = ts_w1[k * 32 + dd];
        }
    }
    __syncthreads();

    int d  = threadIdx.x;
    int ty = threadIdx.y;

    float acc1[4], acc2[4];
    float b1a = is_sp ? 0.f : st_b1[d];
    float b1b = is_sp ? 0.f : ts_b1[d];
    #pragma unroll
    for (int rr = 0; rr < 4; ++rr) { acc1[rr] = b1a; acc2[rr] = b1b; }

    #pragma unroll 4
    for (int k = 0; k < 32; ++k) {
        float wav = wa[k * 32 + d];
        float wbv = wb[k * 32 + d];
        #pragma unroll
        for (int rr = 0; rr < 4; ++rr) {
            float x = xs[(ty + 8 * rr) * 33 + k];
            acc1[rr] = fmaf(x, wav, acc1[rr]);
            acc2[rr] = fmaf(x, wbv, acc2[rr]);
        }
    }

    float* o1 = is_sp ? g_sa : g_sb;
    float* o2 = is_sp ? g_tb : g_ta;
    size_t base = is_sp ? (size_t)gr0 : (size_t)(gr0 - Bc * Nc);
    #pragma unroll
    for (int rr = 0; rr < 4; ++rr) {
        size_t r = base + ty + 8 * rr;
        o1[r * 32 + d] = 0.5f * acc1[rr];
        o2[r * 32 + d] = 0.5f * acc2[rr];
    }
}

// ---------------------------------------------------------------------------
// Fused kernel. Work list (4384 blocks):
//   idx < 4352: period-17 interleave — r<9: gram half-block (2304 total,
//               upper-triangle supertiles, mirrored), else pair (2048 total,
//               32x64 tiles, d-blocked float4).
//   idx >= 4352: gram BR (32).
// ---------------------------------------------------------------------------
__global__ void __launch_bounds__(256, 4)
fused_kernel(const float* __restrict__ sp, const float* __restrict__ tp,
             const float* __restrict__ st_w2, const float* __restrict__ st_b2,
             const float* __restrict__ ts_w2, const float* __restrict__ ts_b2,
             float* __restrict__ out)
{
    __shared__ __align__(16) float sbuf[6400];   // 25.6 KB
    int idx = blockIdx.x;
    int tid = threadIdx.x;

    if (idx < 4352) {
        int q = idx / 17, r = idx % 17;

        if (r < 9) {
            // ------------- gram TL: tanh(relu(S @ S^T)), 64x128 tile --------
            int g = q * 9 + r;          // 0..2303
            int b = g / 72, t = g % 72;

            int r0, c0; bool mirror;
            if (t < 16) {               // diagonal supertile halves
                int st = t >> 1;
                r0 = st * 128 + (t & 1) * 64;
                c0 = st * 128;
                mirror = false;
            } else {                    // off-diagonal upper supertiles
                int o = t - 16;
                int u = o >> 1;         // 0..27 -> (R,C), R<C
                int R = 0, rem = u;
                while (rem >= 7 - R) { rem -= 7 - R; ++R; }
                int C = R + 1 + rem;
                r0 = R * 128 + (o & 1) * 64;
                c0 = C * 128;
                mirror = true;
            }

            int tx = tid & 15;
            int ty = tid >> 4;

            float* At = sbuf;           // [32][68]  k-major
            float* Bt = sbuf + 2176;    // [32][132] k-major

            const float* Xb = sp + (size_t)b * Nc * Dc;
            for (int i = tid; i < 2048; i += 256) {
                int row = i >> 5, k = i & 31;
                At[k * 68 + row] = Xb[(size_t)(r0 + row) * 32 + k];
            }
            for (int i = tid; i < 4096; i += 256) {
                int row = i >> 5, k = i & 31;
                Bt[k * 132 + row] = Xb[(size_t)(c0 + row) * 32 + k];
            }
            __syncthreads();

            unsigned at_u = (unsigned)__cvta_generic_to_shared(At) + ty * 16u;
            unsigned bt_u = (unsigned)__cvta_generic_to_shared(Bt) + tx * 16u;

            unsigned long long c2[4][4];
            #pragma unroll
            for (int i = 0; i < 4; ++i)
                #pragma unroll
                for (int p = 0; p < 4; ++p) c2[i][p] = 0ull;

            #pragma unroll 4
            for (int k = 0; k < 32; ++k) {
                float a0, a1, a2, a3;
                asm("ld.shared.v4.b32 {%0,%1,%2,%3}, [%4];"
                    : "=f"(a0), "=f"(a1), "=f"(a2), "=f"(a3)
                    : "r"(at_u + (unsigned)(k * 272)));
                unsigned long long av2[4], bv2[4];
                asm("mov.b64 %0, {%1, %1};" : "=l"(av2[0]) : "f"(a0));
                asm("mov.b64 %0, {%1, %1};" : "=l"(av2[1]) : "f"(a1));
                asm("mov.b64 %0, {%1, %1};" : "=l"(av2[2]) : "f"(a2));
                asm("mov.b64 %0, {%1, %1};" : "=l"(av2[3]) : "f"(a3));
                asm("ld.shared.v2.b64 {%0,%1}, [%2];"
                    : "=l"(bv2[0]), "=l"(bv2[1])
                    : "r"(bt_u + (unsigned)(k * 528)));
                asm("ld.shared.v2.b64 {%0,%1}, [%2];"
                    : "=l"(bv2[2]), "=l"(bv2[3])
                    : "r"(bt_u + (unsigned)(k * 528 + 256)));
                #pragma unroll
                for (int i = 0; i < 4; ++i)
                    #pragma unroll
                    for (int p = 0; p < 4; ++p)
                        asm("fma.rn.f32x2 %0, %1, %2, %0;"
                            : "+l"(c2[i][p]) : "l"(av2[i]), "l"(bv2[p]));
            }
            __syncthreads();   // sbuf reuse for transpose staging below

            float* ob = out + (size_t)b * NTc * NTc;

            #pragma unroll
            for (int h = 0; h < 2; ++h) {       // column halves 0-63, 64-127
                float va[4][4];                 // [row i][col c]
                #pragma unroll
                for (int i = 0; i < 4; ++i) {
                    float l0, h0, l1, h1;
                    asm("mov.b64 {%0, %1}, %2;" : "=f"(l0), "=f"(h0) : "l"(c2[i][2*h]));
                    asm("mov.b64 {%0, %1}, %2;" : "=f"(l1), "=f"(h1) : "l"(c2[i][2*h+1]));
                    va[i][0] = tanh_relu(l0); va[i][1] = tanh_relu(h0);
                    va[i][2] = tanh_relu(l1); va[i][3] = tanh_relu(h1);
                }
                #pragma unroll
                for (int i = 0; i < 4; ++i) {
                    float4 v;
                    v.x = va[i][0]; v.y = va[i][1]; v.z = va[i][2]; v.w = va[i][3];
                    *reinterpret_cast<float4*>(
                        ob + (size_t)(r0 + 4 * ty + i) * NTc + c0 + 64 * h + 4 * tx) = v;
                }
                if (mirror) {
                    #pragma unroll
                    for (int c = 0; c < 4; ++c) {
                        float4 v;
                        v.x = va[0][c]; v.y = va[1][c]; v.z = va[2][c]; v.w = va[3][c];
                        *reinterpret_cast<float4*>(sbuf + (4 * tx + c) * 68 + 4 * ty) = v;
                    }
                    __syncthreads();
                    int w = tid >> 5, l = tid & 31;
                    int sr = l >> 4, off = (l & 15) * 4;
                    #pragma unroll
                    for (int j = 0; j < 4; ++j) {
                        int row = 8 * w + 2 * j + sr;
                        float4 v = *reinterpret_cast<float4*>(sbuf + row * 68 + off);
                        *reinterpret_cast<float4*>(
                            ob + (size_t)(c0 + 64 * h + row) * NTc + r0 + off) = v;
                    }
                    __syncthreads();
                }
            }
        } else {
            // ----------- bilinear MLP pair blocks: 32x64 tile ---------------
            // out = tanh(relu( wconst + 0.5*sum_d w2[d]*tanh(A+B) ))
            int p = q * 8 + (r - 9);    // 0..2047
            int RA, CB, ROFF, COFF, r0, c0, b;
            const float *Arow, *Bcol, *w2, *b2;
            if (p < 1024) {            // st: rows spatial, cols temporal
                b = p >> 5; r0 = (p & 31) * 32; c0 = 0;
                RA = Nc; CB = Tc; ROFF = 0; COFF = Nc;
                Arow = g_sa; Bcol = g_sb; w2 = st_w2; b2 = st_b2;
            } else {                   // ts: rows temporal, cols spatial
                int s2 = p - 1024;
                b = s2 >> 5;
                int sub = s2 & 31;
                r0 = (sub & 1) * 32; c0 = (sub >> 1) * 64;
                RA = Tc; CB = Nc; ROFF = Nc; COFF = 0;
                Arow = g_ta; Bcol = g_tb; w2 = ts_w2; b2 = ts_b2;
            }

            float* rs  = sbuf;          // [32][36]  (pad 36 for v4 align)
            float* cs  = sbuf + 1152;   // [64][36]
            float* w2s = sbuf + 3456;   // [32]
            float* wcp = sbuf + 3488;   // [1]

            for (int i = tid; i < 1024; i += 256)
                rs[(i >> 5) * 36 + (i & 31)] =
                    Arow[((size_t)b * RA + r0 + (i >> 5)) * 32 + (i & 31)];
            for (int i = tid; i < 2048; i += 256)
                cs[(i >> 5) * 36 + (i & 31)] =
                    Bcol[((size_t)b * CB + c0 + (i >> 5)) * 32 + (i & 31)];
            if (tid < 32) w2s[tid] = w2[tid];
            __syncthreads();
            if (tid == 0) {
                float s = 0.f;
                #pragma unroll
                for (int d = 0; d < 32; ++d) s += w2s[d];
                wcp[0] = fmaf(0.5f, s, b2[0]);   // b2 + 0.5*sum(w2)
            }
            __syncthreads();

            int tc = tid & 63;   // column in tile
            int tr = tid >> 6;   // row group 0..3; rows tr + 4*ii

            const float4* w2v = reinterpret_cast<const float4*>(w2s);
            const float4* cv4 = reinterpret_cast<const float4*>(cs + tc * 36);

            float acc[8];
            #pragma unroll
            for (int ii = 0; ii < 8; ++ii) acc[ii] = 0.f;

            #pragma unroll
            for (int dq = 0; dq < 8; ++dq) {
                float4 wv = w2v[dq];
                float4 cv = cv4[dq];
                #pragma unroll
                for (int ii = 0; ii < 8; ++ii) {
                    float4 rv = *reinterpret_cast<const float4*>(
                        rs + (tr + 4 * ii) * 36 + dq * 4);
                    float s;
                    s  = wv.x * tanh_ap(rv.x + cv.x);
                    s  = fmaf(wv.y, tanh_ap(rv.y + cv.y), s);
                    s  = fmaf(wv.z, tanh_ap(rv.z + cv.z), s);
                    s  = fmaf(wv.w, tanh_ap(rv.w + cv.w), s);
                    acc[ii] += s;
                }
            }

            float wconst = wcp[0];
            float* ob = out + (size_t)b * NTc * NTc;
            #pragma unroll
            for (int ii = 0; ii < 8; ++ii)
                ob[(size_t)(ROFF + r0 + tr + 4 * ii) * NTc + (COFF + c0 + tc)]
                    = tanh_relu(fmaf(0.5f, acc[ii], wconst));
        }
    } else {
        // ------------------- gram BR: tanh(relu(T @ T^T)) -------------------
        int b = idx - 4352;
        float* ts_s = sbuf;   // [64][33]
        const float* tb = tp + (size_t)b * Tc * Dc;
        for (int i = tid; i < 2048; i += 256)
            ts_s[(i >> 5) * 33 + (i & 31)] = tb[i];
        __syncthreads();

        float* ob = out + (size_t)b * NTc * NTc;
        for (int it = 0; it < 16; ++it) {
            int e = tid + 256 * it;
            int i = e >> 6, j = e & 63;
            float acc = 0.f;
            #pragma unroll
            for (int k = 0; k < 32; ++k)
                acc = fmaf(ts_s[i * 33 + k], ts_s[j * 33 + k], acc);
            ob[(size_t)(Nc + i) * NTc + (Nc + j)] = tanh_relu(acc);
        }
    }
}

// ---------------------------------------------------------------------------
extern "C" void kernel_launch(void* const* d_in, const int* in_sizes, int n_in,
                              void* d_out, int out_size)
{
    const float* sp    = (const float*)d_in[0];
    const float* tp    = (const float*)d_in[1];
    const float* st_w1 = (const float*)d_in[2];
    const float* st_b1 = (const float*)d_in[3];
    const float* st_w2 = (const float*)d_in[4];
    const float* st_b2 = (const float*)d_in[5];
    const float* ts_w1 = (const float*)d_in[6];
    const float* ts_b1 = (const float*)d_in[7];
    const float* ts_w2 = (const float*)d_in[8];
    const float* ts_b2 = (const float*)d_in[9];
    float* out = (float*)d_out;

    proj_kernel<<<dim3((Bc * (Nc + Tc)) / 32), dim3(32, 8)>>>(sp, tp, st_w1, st_b1, ts_w1, ts_b1);
    fused_kernel<<<4384, 256>>>(sp, tp, st_w2, st_b2, ts_w2, ts_b2, out);
}